// round 14
// baseline (speedup 1.0000x reference)
#include <cuda_runtime.h>
#include <cstdint>

// embedding_bag(mode='mean'): B bags over a [V,64] fp32 table.
//
// Shape (empirically optimal over 13 tuning rounds on GB300/sm_103a):
//   - One HALF-WARP per bag; sublane s (0..15) owns one float4 (cols 4s..4s+3).
//     16 lanes x 16B = one full 256B row per half-warp; each warp LDG.E.128
//     covers TWO rows (512B per instruction).
//   - Unroll x4 (2KB in flight per warp) + 2-wide tail (L=50 = 12*4+2).
//   - 256-thread CTAs, 32 regs, 8 CTAs/SM.
//   - Persistent grid of exactly 148*8 = 1184 CTAs (one full wave, 8 CTAs on
//     EVERY SM) with warp-level grid-stride over bag pairs. (R13's clamp bug
//     silently reduced this to 1024 CTAs; fixed — only bound by bag-pairs.)
//   - Row addresses are u32 BYTE offsets (V*256B = 256MB fits u32).
//
// Cache policy (intrinsics only — asm volatile in the hot loop blocks ptxas
// index-load batching, measured +2.1us):
//   - weight gathers: __ldcg (L2-only; L1 hit ~0% on a 143MB random footprint)
//   - output: __stcs (write-once streaming)
//   - indices/offsets: __ldg

#define NUM_SMS 148
#define CTAS_PER_SM 8

template <typename IDX>
static __device__ __forceinline__ void process_bag(
    const IDX* __restrict__ idx,
    const char* __restrict__ wbase,
    float* __restrict__ out,
    int sub, int bag,
    long long start, long long end)
{
    float4 acc = make_float4(0.f, 0.f, 0.f, 0.f);

    long long i = start;
    #pragma unroll 1
    for (; i + 4 <= end; i += 4) {
        unsigned o0 = (unsigned)__ldg(&idx[i    ]) << 8;
        unsigned o1 = (unsigned)__ldg(&idx[i + 1]) << 8;
        unsigned o2 = (unsigned)__ldg(&idx[i + 2]) << 8;
        unsigned o3 = (unsigned)__ldg(&idx[i + 3]) << 8;
        float4 v0 = __ldcg((const float4*)(wbase + o0));
        float4 v1 = __ldcg((const float4*)(wbase + o1));
        float4 v2 = __ldcg((const float4*)(wbase + o2));
        float4 v3 = __ldcg((const float4*)(wbase + o3));
        acc.x += (v0.x + v1.x) + (v2.x + v3.x);
        acc.y += (v0.y + v1.y) + (v2.y + v3.y);
        acc.z += (v0.z + v1.z) + (v2.z + v3.z);
        acc.w += (v0.w + v1.w) + (v2.w + v3.w);
    }
    if (i + 2 <= end) {
        unsigned o0 = (unsigned)__ldg(&idx[i    ]) << 8;
        unsigned o1 = (unsigned)__ldg(&idx[i + 1]) << 8;
        float4 v0 = __ldcg((const float4*)(wbase + o0));
        float4 v1 = __ldcg((const float4*)(wbase + o1));
        acc.x += v0.x + v1.x;
        acc.y += v0.y + v1.y;
        acc.z += v0.z + v1.z;
        acc.w += v0.w + v1.w;
        i += 2;
    }
    if (i < end) {
        unsigned o = (unsigned)__ldg(&idx[i]) << 8;
        float4 v = __ldcg((const float4*)(wbase + o));
        acc.x += v.x; acc.y += v.y; acc.z += v.z; acc.w += v.w;
    }

    const long long cnt = end - start;
    const float inv = 1.0f / (float)(cnt > 0 ? cnt : 1);
    acc.x *= inv; acc.y *= inv; acc.z *= inv; acc.w *= inv;

    __stcs(((float4*)out) + (size_t)bag * 16 + sub, acc);
}

template <typename IDX>
static __device__ __forceinline__ void run_all(
    const IDX* __restrict__ idx,
    const IDX* __restrict__ off,
    const char* __restrict__ weight_bytes,
    float* __restrict__ out,
    int num_bags, long long total_indices,
    int warp_global, int total_warps, int half, int sub)
{
    const char* __restrict__ wbase = weight_bytes + (unsigned)(sub * 16);
    // Grid-stride over bag pairs: warp w handles bag 2w+half, then strides.
    for (int bag = 2 * warp_global + half; bag < num_bags; bag += 2 * total_warps) {
        long long start = (long long)__ldg(&off[bag]);
        long long end   = (bag + 1 < num_bags) ? (long long)__ldg(&off[bag + 1])
                                               : total_indices;
        process_bag<IDX>(idx, wbase, out, sub, bag, start, end);
    }
}

__global__ __launch_bounds__(256, 8)
void embag_mean_kernel(const void* __restrict__ indices_raw,
                       const void* __restrict__ offsets_raw,
                       const char* __restrict__ weight_bytes,
                       float* __restrict__ out,
                       int num_bags, long long total_indices) {
    const int warp_global = (int)((blockIdx.x * (unsigned)blockDim.x + threadIdx.x) >> 5);
    const int total_warps = (int)((gridDim.x * (unsigned)blockDim.x) >> 5);
    const int lane = threadIdx.x & 31;
    const int half = lane >> 4;        // bag within the warp
    const int sub  = lane & 15;        // float4 column group within the row

    // Inline dtype detection (int64 vs int32 indices): ids < 2^31, so an
    // int64 LE buffer has every odd 32-bit word zero; an int32 buffer has
    // random nonzero ids there (P[all 4 zero] ~ 1e-24). Uniform result.
    const int* wprobe = (const int*)indices_raw;
    int allz = 1;
    #pragma unroll
    for (int k = 1; k < 9; k += 2) allz &= (__ldg(&wprobe[k]) == 0);

    if (allz) {
        run_all<long long>((const long long*)indices_raw,
                           (const long long*)offsets_raw,
                           weight_bytes, out, num_bags, total_indices,
                           warp_global, total_warps, half, sub);
    } else {
        run_all<int>((const int*)indices_raw,
                     (const int*)offsets_raw,
                     weight_bytes, out, num_bags, total_indices,
                     warp_global, total_warps, half, sub);
    }
}

extern "C" void kernel_launch(void* const* d_in, const int* in_sizes, int n_in,
                              void* d_out, int out_size) {
    // metadata order: indices [T], offsets [B], weight [V*D]
    const void* indices = d_in[0];
    const void* offsets = d_in[1];
    const char* weight  = (const char*)d_in[2];
    float*      out     = (float*)d_out;

    const int       num_bags      = in_sizes[1];
    const long long total_indices = in_sizes[0];

    // One full, perfectly balanced wave: 8 CTAs on every SM.
    // Only bound by the number of bag PAIRS (each warp needs >=1 pair at most;
    // surplus warps exit immediately and are evenly spread across SMs).
    int blocks = NUM_SMS * CTAS_PER_SM;          // 1184
    const int pairs = (num_bags + 1) / 2;        // 8192
    const int max_useful = (pairs + 8 - 1) / 8;  // CTAs with >=1 working warp
    if (blocks > max_useful) blocks = max_useful;

    embag_mean_kernel<<<blocks, 256>>>(indices, offsets, weight, out,
                                       num_bags, total_indices);
}